// round 2
// baseline (speedup 1.0000x reference)
#include <cuda_runtime.h>
#include <math.h>

#define HD    768
#define NB    4
#define SEQ   256
#define MROWS 1024        // NB*SEQ
#define TOPK  4
#define NL    4
#define LOGITS_SZ (NB*SEQ*SEQ)   // 262144

#define NEG_INF __int_as_float(0xff800000)

// Scratch (allocation-free rule: __device__ globals)
__device__ float g_Ti[MROWS*HD];
__device__ float g_Tj[MROWS*HD];
__device__ float g_P [MROWS*HD];
__device__ float g_Q [MROWS*HD];
__device__ int   g_idx[MROWS*TOPK];

__device__ __forceinline__ float frcp_(float x){ float r; asm("rcp.approx.f32 %0, %1;" : "=f"(r) : "f"(x)); return r; }
__device__ __forceinline__ float fex2_(float x){ float r; asm("ex2.approx.f32 %0, %1;" : "=f"(r) : "f"(x)); return r; }

// Accurate tanh independent of -use_fast_math lowering of tanhf().
// abs err ~3e-7 uniformly; tanh(x) = sign(x) * (1 - 2/(e^{2|x|}+1))
__device__ __forceinline__ float tanh_acc(float x){
    float ax = fabsf(x);
    float E  = fex2_(ax * 2.8853901f);      // 2*log2(e)
    float r  = frcp_(E + 1.0f);
    float y  = fmaf(-2.0f, r, 1.0f);
    return copysignf(y, x);
}

// ---------------------------------------------------------------------------
// Kernel 1: fused 4-way GEMM  Y = X @ [Wa | Ua | Wd | Wh]^T  (all N-tiles of 64
// fall entirely inside one group since 768 % 64 == 0).
//   group 0: Ti = tanh(X Wa^T + Wa_b)
//   group 1: Tj = tanh(X Ua^T + Ua_b)
//   group 2: P  = X Wd^T + dense_b     (Wd = dense_w[:, :768])
//   group 3: Q  = X Wh^T               (Wh = dense_w[:, 768:])
// BM=128 BN=64 BK=16, 256 threads, 8x4 microtile.
// ---------------------------------------------------------------------------
#define BM 128
#define BN 64
#define BKG 16

__global__ __launch_bounds__(256) void gemm4_kernel(
    const float* __restrict__ X,  const float* __restrict__ Wa,
    const float* __restrict__ Ua, const float* __restrict__ Dw,
    const float* __restrict__ Wab,const float* __restrict__ Uab,
    const float* __restrict__ Db)
{
    __shared__ float As[BKG][BM];
    __shared__ float Bs[BKG][BN];

    const int tid  = threadIdx.x;
    const int n4   = blockIdx.x * BN;        // 0..3071
    const int m0   = blockIdx.y * BM;
    const int group= n4 / HD;                // 0..3
    const int ng0  = n4 - group * HD;

    const float* Wp; int ld, coff;
    if      (group == 0){ Wp = Wa; ld = HD;   coff = 0;  }
    else if (group == 1){ Wp = Ua; ld = HD;   coff = 0;  }
    else if (group == 2){ Wp = Dw; ld = 2*HD; coff = 0;  }
    else                { Wp = Dw; ld = 2*HD; coff = HD; }

    const int lrow = tid >> 2;               // 0..63
    const int lvec = tid & 3;                // 0..3  (float4 slot along k)
    const int tx   = tid & 15;               // n dir
    const int ty   = tid >> 4;               // m dir

    float acc[8][4];
    #pragma unroll
    for (int i = 0; i < 8; i++)
        #pragma unroll
        for (int j = 0; j < 4; j++) acc[i][j] = 0.0f;

    for (int k0 = 0; k0 < HD; k0 += BKG) {
        float4 a0 = *(const float4*)&X [(m0 + lrow     ) * HD + k0 + lvec*4];
        float4 a1 = *(const float4*)&X [(m0 + lrow + 64) * HD + k0 + lvec*4];
        float4 b0 = *(const float4*)&Wp[(ng0 + lrow) * ld + coff + k0 + lvec*4];

        __syncthreads();
        #pragma unroll
        for (int j = 0; j < 4; j++) {
            As[lvec*4 + j][lrow     ] = ((const float*)&a0)[j];
            As[lvec*4 + j][lrow + 64] = ((const float*)&a1)[j];
            Bs[lvec*4 + j][lrow     ] = ((const float*)&b0)[j];
        }
        __syncthreads();

        #pragma unroll
        for (int k = 0; k < BKG; k++) {
            float ar[8], br[4];
            *(float4*)&ar[0] = *(const float4*)&As[k][ty*8];
            *(float4*)&ar[4] = *(const float4*)&As[k][ty*8 + 4];
            *(float4*)&br[0] = *(const float4*)&Bs[k][tx*4];
            #pragma unroll
            for (int i = 0; i < 8; i++)
                #pragma unroll
                for (int j = 0; j < 4; j++)
                    acc[i][j] = fmaf(ar[i], br[j], acc[i][j]);
        }
    }

    float* dst; const float* bias; int do_tanh;
    if      (group == 0){ dst = g_Ti; bias = Wab; do_tanh = 1; }
    else if (group == 1){ dst = g_Tj; bias = Uab; do_tanh = 1; }
    else if (group == 2){ dst = g_P;  bias = Db;  do_tanh = 0; }
    else                { dst = g_Q;  bias = 0;   do_tanh = 0; }

    #pragma unroll
    for (int i = 0; i < 8; i++) {
        const int m = m0 + ty*8 + i;
        #pragma unroll
        for (int j = 0; j < 4; j++) {
            const int n = ng0 + tx*4 + j;
            float v = acc[i][j];
            if (bias)    v += bias[n];
            if (do_tanh) v  = tanh_acc(v);
            dst[m * HD + n] = v;
        }
    }
}

// ---------------------------------------------------------------------------
// Kernel 2: biaffine logits via tanh addition identity.
// logits[b,a,c] = sum_h v[h] * (Ti[c,h]+Tj[a,h]) / (1 + Ti[c,h]*Tj[a,h])
// 32x32 (a,c) tile per block, 128 threads, 2x4 microtile. MUFU.RCP-bound.
// ---------------------------------------------------------------------------
__global__ __launch_bounds__(128) void biaffine_kernel(
    const float* __restrict__ va, float* __restrict__ out)
{
    __shared__ float Tjs[32][33];
    __shared__ float Tis[32][33];
    __shared__ float vs[32];

    const int b  = blockIdx.z;
    const int a0 = blockIdx.y * 32;
    const int c0 = blockIdx.x * 32;
    const int tid = threadIdx.x;
    const int la  = tid >> 3;      // 0..15 -> a pair
    const int lc  = tid & 7;       // 0..7  -> c quad
    const int lrow = tid >> 2;     // 0..31
    const int lvec = tid & 3;      // 0..3

    const float* TjB = g_Tj + (size_t)(b*SEQ + a0) * HD;
    const float* TiB = g_Ti + (size_t)(b*SEQ + c0) * HD;

    float acc[2][4] = {{0.f,0.f,0.f,0.f},{0.f,0.f,0.f,0.f}};

    for (int k0 = 0; k0 < HD; k0 += 32) {
        float4 ja = *(const float4*)&TjB[lrow*HD + k0 + lvec*8];
        float4 jb = *(const float4*)&TjB[lrow*HD + k0 + lvec*8 + 4];
        float4 ia = *(const float4*)&TiB[lrow*HD + k0 + lvec*8];
        float4 ib = *(const float4*)&TiB[lrow*HD + k0 + lvec*8 + 4];
        __syncthreads();
        #pragma unroll
        for (int j = 0; j < 4; j++) {
            Tjs[lrow][lvec*8 + j]     = ((const float*)&ja)[j];
            Tjs[lrow][lvec*8 + 4 + j] = ((const float*)&jb)[j];
            Tis[lrow][lvec*8 + j]     = ((const float*)&ia)[j];
            Tis[lrow][lvec*8 + 4 + j] = ((const float*)&ib)[j];
        }
        if (tid < 32) vs[tid] = va[k0 + tid];
        __syncthreads();

        #pragma unroll 8
        for (int h = 0; h < 32; h++) {
            const float vv  = vs[h];
            const float tb0 = Tjs[la*2    ][h];
            const float tb1 = Tjs[la*2 + 1][h];
            float tc[4];
            #pragma unroll
            for (int j = 0; j < 4; j++) tc[j] = Tis[lc*4 + j][h];
            #pragma unroll
            for (int j = 0; j < 4; j++) {
                {
                    float num = tc[j] + tb0;
                    float den = fmaf(tc[j], tb0, 1.0f);
                    acc[0][j] = fmaf(vv, num * frcp_(den), acc[0][j]);
                }
                {
                    float num = tc[j] + tb1;
                    float den = fmaf(tc[j], tb1, 1.0f);
                    acc[1][j] = fmaf(vv, num * frcp_(den), acc[1][j]);
                }
            }
        }
    }

    #pragma unroll
    for (int i = 0; i < 2; i++) {
        float4 w = make_float4(acc[i][0], acc[i][1], acc[i][2], acc[i][3]);
        *(float4*)&out[((size_t)(b*SEQ + a0 + la*2 + i)) * SEQ + c0 + lc*4] = w;
    }
}

// ---------------------------------------------------------------------------
// Kernel 3: per-row top-4 (jax semantics: descending, ties -> smallest index).
// One warp per row of 256 logits.
// ---------------------------------------------------------------------------
__global__ __launch_bounds__(256) void topk_kernel(const float* __restrict__ logits)
{
    const int row  = blockIdx.x * 8 + (threadIdx.x >> 5);
    const int lane = threadIdx.x & 31;
    const float* p = logits + (size_t)row * SEQ;

    float v[8];
    #pragma unroll
    for (int j = 0; j < 8; j++) v[j] = p[j*32 + lane];

    #pragma unroll
    for (int k = 0; k < TOPK; k++) {
        float bv = NEG_INF; int bi = 1 << 30;
        #pragma unroll
        for (int j = 0; j < 8; j++) {
            const int idx = j*32 + lane;
            if (v[j] > bv || (v[j] == bv && idx < bi)) { bv = v[j]; bi = idx; }
        }
        #pragma unroll
        for (int off = 16; off > 0; off >>= 1) {
            float ov = __shfl_down_sync(0xffffffffu, bv, off);
            int   oi = __shfl_down_sync(0xffffffffu, bi, off);
            if (ov > bv || (ov == bv && oi < bi)) { bv = ov; bi = oi; }
        }
        bi = __shfl_sync(0xffffffffu, bi, 0);
        if (lane == 0) g_idx[row*TOPK + k] = bi;
        if ((bi & 31) == lane) {
            const int slot = bi >> 5;
            #pragma unroll
            for (int j = 0; j < 8; j++) if (j == slot) v[j] = NEG_INF;
        }
    }
}

// ---------------------------------------------------------------------------
// Kernel 4: dependency type logits.
// hidden[b,s,m] = tanh(P[b,s] + Q[b,idx[b,s,m]])   (P carries dense_b)
// type_logits   = hidden @ fc_w^T + fc_b
// One warp per (row, m); 4 accumulators (L=4).
// ---------------------------------------------------------------------------
__global__ __launch_bounds__(128) void typelogits_kernel(
    const float* __restrict__ fw, const float* __restrict__ fb,
    float* __restrict__ out)
{
    const int row  = blockIdx.x;            // b*SEQ + s
    const int m    = threadIdx.x >> 5;      // candidate 0..3
    const int lane = threadIdx.x & 31;
    const int b    = row >> 8;

    const int hidx = g_idx[row*TOPK + m];
    const float* Prow = g_P + (size_t)row * HD;
    const float* Qrow = g_Q + (size_t)(b*SEQ + hidx) * HD;

    float a0=0.f, a1=0.f, a2=0.f, a3=0.f;
    for (int h = lane; h < HD; h += 32) {
        const float t = tanh_acc(Prow[h] + Qrow[h]);
        a0 = fmaf(t, fw[h       ], a0);
        a1 = fmaf(t, fw[h +   HD], a1);
        a2 = fmaf(t, fw[h + 2*HD], a2);
        a3 = fmaf(t, fw[h + 3*HD], a3);
    }
    #pragma unroll
    for (int off = 16; off > 0; off >>= 1) {
        a0 += __shfl_down_sync(0xffffffffu, a0, off);
        a1 += __shfl_down_sync(0xffffffffu, a1, off);
        a2 += __shfl_down_sync(0xffffffffu, a2, off);
        a3 += __shfl_down_sync(0xffffffffu, a3, off);
    }
    if (lane == 0) {
        float* o = out + LOGITS_SZ + (size_t)(row*TOPK + m) * NL;
        o[0] = a0 + fb[0];
        o[1] = a1 + fb[1];
        o[2] = a2 + fb[2];
        o[3] = a3 + fb[3];
    }
}

// ---------------------------------------------------------------------------
extern "C" void kernel_launch(void* const* d_in, const int* in_sizes, int n_in,
                              void* d_out, int out_size)
{
    const float* X   = (const float*)d_in[0];
    const float* Wa  = (const float*)d_in[1];
    const float* Wab = (const float*)d_in[2];
    const float* Ua  = (const float*)d_in[3];
    const float* Uab = (const float*)d_in[4];
    const float* va  = (const float*)d_in[5];
    const float* Dw  = (const float*)d_in[6];
    const float* Db  = (const float*)d_in[7];
    const float* fw  = (const float*)d_in[8];
    const float* fb  = (const float*)d_in[9];
    float* out = (float*)d_out;

    dim3 g1(4*HD / BN, MROWS / BM);          // 48 x 8
    gemm4_kernel<<<g1, 256>>>(X, Wa, Ua, Dw, Wab, Uab, Db);

    dim3 g2(SEQ/32, SEQ/32, NB);             // 8 x 8 x 4
    biaffine_kernel<<<g2, 128>>>(va, out);

    topk_kernel<<<MROWS/8, 256>>>(out);

    typelogits_kernel<<<MROWS, 128>>>(fw, fb, out);
}

// round 7
// speedup vs baseline: 1.8971x; 1.8971x over previous
#include <cuda_runtime.h>
#include <cuda_bf16.h>
#include <math.h>
#include <stdint.h>
#include <cstdint>

#define HD    768
#define NB    4
#define SEQ   256
#define MROWS 1024        // NB*SEQ
#define NCOLS 3072        // 4 groups * HD
#define TOPK  4
#define NL    4
#define LOGITS_SZ (NB*SEQ*SEQ)   // 262144

#define NEG_INF __int_as_float(0xff800000)

// ------------------------- device scratch (no allocs) -----------------------
__device__ float g_Ti[MROWS*HD];
__device__ float g_Tj[MROWS*HD];
__device__ float g_P [MROWS*HD];
__device__ float g_Q [MROWS*HD];
__device__ int   g_idx[MROWS*TOPK];

// bf16 3-way splits of activations (A) and stacked weights (B)
__device__ __nv_bfloat16 g_A0[MROWS*HD], g_A1[MROWS*HD], g_A2[MROWS*HD];
__device__ __nv_bfloat16 g_B0[NCOLS*HD], g_B1[NCOLS*HD], g_B2[NCOLS*HD];

// ------------------------- small helpers ------------------------------------
__device__ __forceinline__ float frcp_(float x){ float r; asm("rcp.approx.f32 %0, %1;" : "=f"(r) : "f"(x)); return r; }
__device__ __forceinline__ float fex2_(float x){ float r; asm("ex2.approx.f32 %0, %1;" : "=f"(r) : "f"(x)); return r; }

// Accurate tanh independent of fast-math lowering; abs err ~3e-7
__device__ __forceinline__ float tanh_acc(float x){
    float ax = fabsf(x);
    float E  = fex2_(ax * 2.8853901f);      // 2*log2(e)
    float r  = frcp_(E + 1.0f);
    float y  = fmaf(-2.0f, r, 1.0f);
    return copysignf(y, x);
}

__device__ __forceinline__ uint32_t smem_u32(const void* p){
    uint32_t a;
    asm("{ .reg .u64 t; cvta.to.shared.u64 t, %1; cvt.u32.u64 %0, t; }" : "=r"(a) : "l"(p));
    return a;
}

__device__ __forceinline__ void cp16(uint32_t saddr, const void* g){
    asm volatile("cp.async.cg.shared.global [%0], [%1], 16;" :: "r"(saddr), "l"(g));
}
#define CP_COMMIT() asm volatile("cp.async.commit_group;" ::: "memory")
#define CP_WAIT1()  asm volatile("cp.async.wait_group 1;" ::: "memory")

__device__ __forceinline__ void ldsm4(uint32_t &r0, uint32_t &r1, uint32_t &r2, uint32_t &r3, uint32_t a){
    asm volatile("ldmatrix.sync.aligned.m8n8.x4.shared.b16 {%0,%1,%2,%3}, [%4];"
        : "=r"(r0), "=r"(r1), "=r"(r2), "=r"(r3) : "r"(a));
}

__device__ __forceinline__ void mma16816(float* d, const uint32_t* a, const uint32_t* b){
    asm volatile(
        "mma.sync.aligned.m16n8k16.row.col.f32.bf16.bf16.f32 "
        "{%0,%1,%2,%3}, {%4,%5,%6,%7}, {%8,%9}, {%0,%1,%2,%3};"
        : "+f"(d[0]), "+f"(d[1]), "+f"(d[2]), "+f"(d[3])
        : "r"(a[0]), "r"(a[1]), "r"(a[2]), "r"(a[3]), "r"(b[0]), "r"(b[1]));
}

// ---------------------------------------------------------------------------
// Prep: 3-way bf16 splits.  x = hi + mid + lo with ~26 effective mantissa bits.
// ---------------------------------------------------------------------------
__global__ __launch_bounds__(256) void splitA_kernel(const float* __restrict__ X)
{
    int i = blockIdx.x * 256 + threadIdx.x;
    if (i >= MROWS*HD) return;
    float x = X[i];
    __nv_bfloat16 h = __float2bfloat16(x);
    float r1 = x - __bfloat162float(h);
    __nv_bfloat16 m = __float2bfloat16(r1);
    float r2 = r1 - __bfloat162float(m);
    g_A0[i] = h; g_A1[i] = m; g_A2[i] = __float2bfloat16(r2);
}

__global__ __launch_bounds__(256) void splitB_kernel(
    const float* __restrict__ Wa, const float* __restrict__ Ua,
    const float* __restrict__ Dw)
{
    int i = blockIdx.x * 256 + threadIdx.x;
    if (i >= NCOLS*HD) return;
    int n = i / HD, k = i - n * HD;
    float x;
    if      (n < 768)  x = Wa[n*HD + k];
    else if (n < 1536) x = Ua[(n-768)*HD + k];
    else if (n < 2304) x = Dw[(size_t)(n-1536)*(2*HD) + k];
    else               x = Dw[(size_t)(n-2304)*(2*HD) + HD + k];
    __nv_bfloat16 h = __float2bfloat16(x);
    float r1 = x - __bfloat162float(h);
    __nv_bfloat16 m = __float2bfloat16(r1);
    float r2 = r1 - __bfloat162float(m);
    g_B0[i] = h; g_B1[i] = m; g_B2[i] = __float2bfloat16(r2);
}

// ---------------------------------------------------------------------------
// mma.sync GEMM: D[1024,3072] = sum over 6 split-products A_si @ B_sj^T.
// CTA tile 128x64, 8 warps (warp tile 32x32, grid 4x2), K-chunk 32, 2-stage
// cp.async pipeline. Epilogue: bias (+tanh) into g_Ti/g_Tj/g_P/g_Q.
// smem row stride 40 bf16 (80B) -> conflict-free ldmatrix.
// ---------------------------------------------------------------------------
#define KB        32
#define NKCH      (HD / KB)        // 24
#define RSTRIDE   40               // bf16 elems per smem row (80 B)
#define A_SPL_B   (128 * 80)       // 10240
#define B_SPL_B   (64 * 80)        // 5120
#define A_STG_B   (3 * A_SPL_B)    // 30720
#define STG_B     (A_STG_B + 3 * B_SPL_B)  // 46080
#define GEMM_SMEM (2 * STG_B)      // 92160

__global__ __launch_bounds__(256, 2) void gemm_mma_kernel(
    const float* __restrict__ Wab, const float* __restrict__ Uab,
    const float* __restrict__ Db)
{
    extern __shared__ char dsm[];
    const uint32_t sbase = smem_u32(dsm);

    const int tid  = threadIdx.x;
    const int wid  = tid >> 5;
    const int lane = tid & 31;
    const int wm   = wid >> 1;          // 0..3 (m)
    const int wn   = wid & 1;           // 0..1 (n)
    const int m0   = blockIdx.y * 128;
    const int n0   = blockIdx.x * 64;

    const __nv_bfloat16* Ap[3] = { g_A0, g_A1, g_A2 };
    const __nv_bfloat16* Bp[3] = { g_B0, g_B1, g_B2 };

    // ---- async loader for one K-chunk into one stage ----
    auto issue_stage = [&](int kc, int buf){
        const uint32_t sb = sbase + buf * STG_B;
        #pragma unroll
        for (int i = 0; i < 9; i++) {
            int o = tid + i * 256;           // 0..2303
            if (o < 1536) {                   // A: 3 splits x 128 rows x 4 segs
                int s   = o >> 9;
                int rem = o & 511;
                int r   = rem >> 2, seg = rem & 3;
                const void* g = Ap[s] + ((size_t)(m0 + r) * HD + kc*KB + seg*8);
                cp16(sb + s*A_SPL_B + r*80 + seg*16, g);
            } else {                          // B: 3 splits x 64 rows x 4 segs
                int o2  = o - 1536;
                int s   = o2 >> 8;
                int rem = o2 & 255;
                int r   = rem >> 2, seg = rem & 3;
                const void* g = Bp[s] + ((size_t)(n0 + r) * HD + kc*KB + seg*8);
                cp16(sb + A_STG_B + s*B_SPL_B + r*80 + seg*16, g);
            }
        }
        CP_COMMIT();
    };

    float acc[2][4][4];
    #pragma unroll
    for (int mt = 0; mt < 2; mt++)
        #pragma unroll
        for (int nt = 0; nt < 4; nt++)
            #pragma unroll
            for (int c = 0; c < 4; c++) acc[mt][nt][c] = 0.0f;

    issue_stage(0, 0);
    issue_stage(1, 1);

    const int SI[6] = {0,0,1,0,1,2};
    const int SJ[6] = {0,1,0,2,1,0};

    // precomputed lane pieces for ldmatrix addressing
    const int a_row = wm*32 + (lane & 15);          // + mt*16
    const int a_cb  = (lane >> 4) * 16;             // bytes
    const int b_row = wn*32 + ((lane >> 4) & 1)*8 + (lane & 7);   // + pair*16
    const int b_cb  = ((lane >> 3) & 1) * 16;       // bytes

    for (int kc = 0; kc < NKCH; kc++) {
        CP_WAIT1();
        __syncthreads();
        const uint32_t sb = sbase + (kc & 1) * STG_B;

        #pragma unroll
        for (int ks = 0; ks < 2; ks++) {
            const uint32_t kbyte = ks*32;
            uint32_t afr[3][2][4];
            uint32_t bfr[3][4][2];
            #pragma unroll
            for (int s = 0; s < 3; s++) {
                #pragma unroll
                for (int mt = 0; mt < 2; mt++) {
                    uint32_t ad = sb + s*A_SPL_B + (a_row + mt*16)*80 + kbyte + a_cb;
                    ldsm4(afr[s][mt][0], afr[s][mt][1], afr[s][mt][2], afr[s][mt][3], ad);
                }
                #pragma unroll
                for (int pr = 0; pr < 2; pr++) {
                    uint32_t bd = sb + A_STG_B + s*B_SPL_B + (b_row + pr*16)*80 + kbyte + b_cb;
                    ldsm4(bfr[s][pr*2][0], bfr[s][pr*2][1],
                          bfr[s][pr*2+1][0], bfr[s][pr*2+1][1], bd);
                }
            }
            #pragma unroll
            for (int p = 0; p < 6; p++) {
                const int si = SI[p], sj = SJ[p];
                #pragma unroll
                for (int mt = 0; mt < 2; mt++)
                    #pragma unroll
                    for (int nt = 0; nt < 4; nt++)
                        mma16816(acc[mt][nt], afr[si][mt], bfr[sj][nt]);
            }
        }

        __syncthreads();
        if (kc + 2 < NKCH) issue_stage(kc + 2, kc & 1);
    }

    // ---- epilogue ----
    const int group = blockIdx.x / 12;
    const int ng0   = (blockIdx.x % 12) * 64;

    float* dst; const float* bias; int do_tanh;
    if      (group == 0){ dst = g_Ti; bias = Wab; do_tanh = 1; }
    else if (group == 1){ dst = g_Tj; bias = Uab; do_tanh = 1; }
    else if (group == 2){ dst = g_P;  bias = Db;  do_tanh = 0; }
    else                { dst = g_Q;  bias = 0;   do_tanh = 0; }

    const int er = lane >> 2;        // 0..7
    const int ec = (lane & 3) * 2;   // 0,2,4,6

    #pragma unroll
    for (int mt = 0; mt < 2; mt++) {
        #pragma unroll
        for (int nt = 0; nt < 4; nt++) {
            const int c = ng0 + wn*32 + nt*8 + ec;
            float b0 = bias ? bias[c]     : 0.0f;
            float b1 = bias ? bias[c + 1] : 0.0f;
            #pragma unroll
            for (int half = 0; half < 2; half++) {
                const int m = m0 + wm*32 + mt*16 + er + half*8;
                float v0 = acc[mt][nt][half*2 + 0] + b0;
                float v1 = acc[mt][nt][half*2 + 1] + b1;
                if (do_tanh) { v0 = tanh_acc(v0); v1 = tanh_acc(v1); }
                float2 w = make_float2(v0, v1);
                *(float2*)&dst[(size_t)m * HD + c] = w;
            }
        }
    }
}

// ---------------------------------------------------------------------------
// Biaffine logits via tanh addition identity.
// logits[b,a,c] = sum_h v[h] * (Ti[c,h]+Tj[a,h]) / (1 + Ti[c,h]*Tj[a,h])
// ---------------------------------------------------------------------------
__global__ __launch_bounds__(128) void biaffine_kernel(
    const float* __restrict__ va, float* __restrict__ out)
{
    __shared__ float Tjs[32][33];
    __shared__ float Tis[32][33];
    __shared__ float vs[32];

    const int b  = blockIdx.z;
    const int a0 = blockIdx.y * 32;
    const int c0 = blockIdx.x * 32;
    const int tid = threadIdx.x;
    const int la  = tid >> 3;
    const int lc  = tid & 7;
    const int lrow = tid >> 2;
    const int lvec = tid & 3;

    const float* TjB = g_Tj + (size_t)(b*SEQ + a0) * HD;
    const float* TiB = g_Ti + (size_t)(b*SEQ + c0) * HD;

    float acc[2][4] = {{0.f,0.f,0.f,0.f},{0.f,0.f,0.f,0.f}};

    for (int k0 = 0; k0 < HD; k0 += 32) {
        float4 ja = *(const float4*)&TjB[lrow*HD + k0 + lvec*8];
        float4 jb = *(const float4*)&TjB[lrow*HD + k0 + lvec*8 + 4];
        float4 ia = *(const float4*)&TiB[lrow*HD + k0 + lvec*8];
        float4 ib = *(const float4*)&TiB[lrow*HD + k0 + lvec*8 + 4];
        __syncthreads();
        #pragma unroll
        for (int j = 0; j < 4; j++) {
            Tjs[lrow][lvec*8 + j]     = ((const float*)&ja)[j];
            Tjs[lrow][lvec*8 + 4 + j] = ((const float*)&jb)[j];
            Tis[lrow][lvec*8 + j]     = ((const float*)&ia)[j];
            Tis[lrow][lvec*8 + 4 + j] = ((const float*)&ib)[j];
        }
        if (tid < 32) vs[tid] = va[k0 + tid];
        __syncthreads();

        #pragma unroll 8
        for (int h = 0; h < 32; h++) {
            const float vv  = vs[h];
            const float tb0 = Tjs[la*2    ][h];
            const float tb1 = Tjs[la*2 + 1][h];
            float tc[4];
            #pragma unroll
            for (int j = 0; j < 4; j++) tc[j] = Tis[lc*4 + j][h];
            #pragma unroll
            for (int j = 0; j < 4; j++) {
                {
                    float num = tc[j] + tb0;
                    float den = fmaf(tc[j], tb0, 1.0f);
                    acc[0][j] = fmaf(vv, num * frcp_(den), acc[0][j]);
                }
                {
                    float num = tc[j] + tb1;
                    float den = fmaf(tc[j], tb1, 1.0f);
                    acc[1][j] = fmaf(vv, num * frcp_(den), acc[1][j]);
                }
            }
        }
    }

    #pragma unroll
    for (int i = 0; i < 2; i++) {
        float4 w = make_float4(acc[i][0], acc[i][1], acc[i][2], acc[i][3]);
        *(float4*)&out[((size_t)(b*SEQ + a0 + la*2 + i)) * SEQ + c0 + lc*4] = w;
    }
}

// ---------------------------------------------------------------------------
// Top-4 per row (jax tie-break: smallest index). One warp per row.
// ---------------------------------------------------------------------------
__global__ __launch_bounds__(256) void topk_kernel(const float* __restrict__ logits)
{
    const int row  = blockIdx.x * 8 + (threadIdx.x >> 5);
    const int lane = threadIdx.x & 31;
    const float* p = logits + (size_t)row * SEQ;

    float v[8];
    #pragma unroll
    for (int j = 0; j < 8; j++) v[j] = p[j*32 + lane];

    #pragma unroll
    for (int k = 0; k < TOPK; k++) {
        float bv = NEG_INF; int bi = 1 << 30;
        #pragma unroll
        for (int j = 0; j < 8; j++) {
            const int idx = j*32 + lane;
            if (v[j] > bv || (v[j] == bv && idx < bi)) { bv = v[j]; bi = idx; }
        }
        #pragma unroll
        for (int off = 16; off > 0; off >>= 1) {
            float ov = __shfl_down_sync(0xffffffffu, bv, off);
            int   oi = __shfl_down_sync(0xffffffffu, bi, off);
            if (ov > bv || (ov == bv && oi < bi)) { bv = ov; bi = oi; }
        }
        bi = __shfl_sync(0xffffffffu, bi, 0);
        if (lane == 0) g_idx[row*TOPK + k] = bi;
        if ((bi & 31) == lane) {
            const int slot = bi >> 5;
            #pragma unroll
            for (int j = 0; j < 8; j++) if (j == slot) v[j] = NEG_INF;
        }
    }
}

// ---------------------------------------------------------------------------
// Type logits: hidden = tanh(P[row] + Q[head]);  out = hidden @ fc_w^T + fc_b
// ---------------------------------------------------------------------------
__global__ __launch_bounds__(128) void typelogits_kernel(
    const float* __restrict__ fw, const float* __restrict__ fb,
    float* __restrict__ out)
{
    const int row  = blockIdx.x;
    const int m    = threadIdx.x >> 5;
    const int lane = threadIdx.x & 31;
    const int b    = row >> 8;

    const int hidx = g_idx[row*TOPK + m];
    const float* Prow = g_P + (size_t)row * HD;
    const float* Qrow = g_Q + (size_t)(b*SEQ + hidx) * HD;

    float a0=0.f, a1=0.f, a2=0.f, a3=0.f;
    for (int h = lane; h < HD; h += 32) {
        const float t = tanh_acc(Prow[h] + Qrow[h]);
        a0 = fmaf(t, fw[h       ], a0);
        a1 = fmaf(t, fw[h +   HD], a1);
        a2 = fmaf(t, fw[h + 2*HD], a2);
        a3 = fmaf(t, fw[h + 3*HD], a3);
    }
    #pragma unroll
    for (int off = 16; off > 0; off >>= 1) {
        a0 += __shfl_down_sync(0xffffffffu, a0, off);
        a1 += __shfl_down_sync(0xffffffffu, a1, off);
        a2 += __shfl_down_sync(0xffffffffu, a2, off);
        a3 += __shfl_down_sync(0xffffffffu, a3, off);
    }
    if (lane == 0) {
        float* o = out + LOGITS_SZ + (size_t)(row*TOPK + m) * NL;
        o[0] = a0 + fb[0];
        o[1] = a1 + fb[1];
        o[2] = a2 + fb[2];
        o[3] = a3 + fb[3];
    }
}

// ---------------------------------------------------------------------------
extern "C" void kernel_launch(void* const* d_in, const int* in_sizes, int n_in,
                              void* d_out, int out_size)
{
    const float* X   = (const float*)d_in[0];
    const float* Wa  = (const float*)d_in[1];
    const float* Wab = (const float*)d_in[2];
    const float* Ua  = (const float*)d_in[3];
    const float* Uab = (const float*)d_in[4];
    const float* va  = (const float*)d_in[5];
    const float* Dw  = (const float*)d_in[6];
    const float* Db  = (const float*)d_in[7];
    const float* fw  = (const float*)d_in[8];
    const float* fb  = (const float*)d_in[9];
    float* out = (float*)d_out;

    cudaFuncSetAttribute(gemm_mma_kernel,
                         cudaFuncAttributeMaxDynamicSharedMemorySize, GEMM_SMEM);

    splitA_kernel<<<(MROWS*HD + 255)/256, 256>>>(X);
    splitB_kernel<<<(NCOLS*HD + 255)/256, 256>>>(Wa, Ua, Dw);

    dim3 gg(NCOLS/64, MROWS/128);            // 48 x 8 = 384 CTAs
    gemm_mma_kernel<<<gg, 256, GEMM_SMEM>>>(Wab, Uab, Db);

    dim3 g2(SEQ/32, SEQ/32, NB);             // 8 x 8 x 4
    biaffine_kernel<<<g2, 128>>>(va, out);

    topk_kernel<<<MROWS/8, 256>>>(out);

    typelogits_kernel<<<MROWS, 128>>>(fw, fb, out);
}

// round 12
// speedup vs baseline: 2.2278x; 1.1744x over previous
#include <cuda_runtime.h>
#include <cuda_bf16.h>
#include <math.h>
#include <stdint.h>
#include <cstdint>

#define HD    768
#define NB    4
#define SEQ   256
#define MROWS 1024        // NB*SEQ
#define NCOLS 3072        // 4 groups * HD
#define TOPK  4
#define NL    4
#define LOGITS_SZ (NB*SEQ*SEQ)   // 262144
#define NHCH  3
#define HCHUNK (HD/NHCH)         // 256

#define NEG_INF __int_as_float(0xff800000)

// ------------------------- device scratch (no allocs) -----------------------
__device__ float g_Ti[MROWS*HD];
__device__ float g_Tj[MROWS*HD];
__device__ float g_P [MROWS*HD];
__device__ float g_Q [MROWS*HD];
__device__ int   g_idx[MROWS*TOPK];
__device__ float g_part[NHCH * LOGITS_SZ];

// bf16 3-way splits of activations (A) and stacked weights (B)
__device__ __nv_bfloat16 g_A0[MROWS*HD], g_A1[MROWS*HD], g_A2[MROWS*HD];
__device__ __nv_bfloat16 g_B0[NCOLS*HD], g_B1[NCOLS*HD], g_B2[NCOLS*HD];

// ------------------------- small helpers ------------------------------------
__device__ __forceinline__ float frcp_(float x){ float r; asm("rcp.approx.f32 %0, %1;" : "=f"(r) : "f"(x)); return r; }
__device__ __forceinline__ float fex2_(float x){ float r; asm("ex2.approx.f32 %0, %1;" : "=f"(r) : "f"(x)); return r; }

// Accurate tanh independent of fast-math lowering; abs err ~3e-7
__device__ __forceinline__ float tanh_acc(float x){
    float ax = fabsf(x);
    float E  = fex2_(ax * 2.8853901f);      // 2*log2(e)
    float r  = frcp_(E + 1.0f);
    float y  = fmaf(-2.0f, r, 1.0f);
    return copysignf(y, x);
}

__device__ __forceinline__ uint32_t smem_u32(const void* p){
    uint32_t a;
    asm("{ .reg .u64 t; cvta.to.shared.u64 t, %1; cvt.u32.u64 %0, t; }" : "=r"(a) : "l"(p));
    return a;
}

__device__ __forceinline__ void cp16(uint32_t saddr, const void* g){
    asm volatile("cp.async.cg.shared.global [%0], [%1], 16;" :: "r"(saddr), "l"(g));
}
#define CP_COMMIT() asm volatile("cp.async.commit_group;" ::: "memory")
#define CP_WAIT1()  asm volatile("cp.async.wait_group 1;" ::: "memory")

__device__ __forceinline__ void ldsm4(uint32_t &r0, uint32_t &r1, uint32_t &r2, uint32_t &r3, uint32_t a){
    asm volatile("ldmatrix.sync.aligned.m8n8.x4.shared.b16 {%0,%1,%2,%3}, [%4];"
        : "=r"(r0), "=r"(r1), "=r"(r2), "=r"(r3) : "r"(a));
}

__device__ __forceinline__ void mma16816(float* d, const uint32_t* a, const uint32_t* b){
    asm volatile(
        "mma.sync.aligned.m16n8k16.row.col.f32.bf16.bf16.f32 "
        "{%0,%1,%2,%3}, {%4,%5,%6,%7}, {%8,%9}, {%0,%1,%2,%3};"
        : "+f"(d[0]), "+f"(d[1]), "+f"(d[2]), "+f"(d[3])
        : "r"(a[0]), "r"(a[1]), "r"(a[2]), "r"(a[3]), "r"(b[0]), "r"(b[1]));
}

// ---------------------------------------------------------------------------
// Prep: 3-way bf16 splits.
// ---------------------------------------------------------------------------
__global__ __launch_bounds__(256) void splitA_kernel(const float* __restrict__ X)
{
    int i = blockIdx.x * 256 + threadIdx.x;
    if (i >= MROWS*HD) return;
    float x = X[i];
    __nv_bfloat16 h = __float2bfloat16(x);
    float r1 = x - __bfloat162float(h);
    __nv_bfloat16 m = __float2bfloat16(r1);
    float r2 = r1 - __bfloat162float(m);
    g_A0[i] = h; g_A1[i] = m; g_A2[i] = __float2bfloat16(r2);
}

__global__ __launch_bounds__(256) void splitB_kernel(
    const float* __restrict__ Wa, const float* __restrict__ Ua,
    const float* __restrict__ Dw)
{
    int i = blockIdx.x * 256 + threadIdx.x;
    if (i >= NCOLS*HD) return;
    int n = i / HD, k = i - n * HD;
    float x;
    if      (n < 768)  x = Wa[n*HD + k];
    else if (n < 1536) x = Ua[(n-768)*HD + k];
    else if (n < 2304) x = Dw[(size_t)(n-1536)*(2*HD) + k];
    else               x = Dw[(size_t)(n-2304)*(2*HD) + HD + k];
    __nv_bfloat16 h = __float2bfloat16(x);
    float r1 = x - __bfloat162float(h);
    __nv_bfloat16 m = __float2bfloat16(r1);
    float r2 = r1 - __bfloat162float(m);
    g_B0[i] = h; g_B1[i] = m; g_B2[i] = __float2bfloat16(r2);
}

// ---------------------------------------------------------------------------
// mma.sync GEMM (unchanged from R7 pass): D[1024,3072] = sum of 6 products.
// ---------------------------------------------------------------------------
#define KB        32
#define NKCH      (HD / KB)        // 24
#define A_SPL_B   (128 * 80)
#define B_SPL_B   (64 * 80)
#define A_STG_B   (3 * A_SPL_B)
#define STG_B     (A_STG_B + 3 * B_SPL_B)
#define GEMM_SMEM (2 * STG_B)      // 92160

__global__ __launch_bounds__(256, 2) void gemm_mma_kernel(
    const float* __restrict__ Wab, const float* __restrict__ Uab,
    const float* __restrict__ Db)
{
    extern __shared__ char dsm[];
    const uint32_t sbase = smem_u32(dsm);

    const int tid  = threadIdx.x;
    const int wid  = tid >> 5;
    const int lane = tid & 31;
    const int wm   = wid >> 1;
    const int wn   = wid & 1;
    const int m0   = blockIdx.y * 128;
    const int n0   = blockIdx.x * 64;

    const __nv_bfloat16* Ap[3] = { g_A0, g_A1, g_A2 };
    const __nv_bfloat16* Bp[3] = { g_B0, g_B1, g_B2 };

    auto issue_stage = [&](int kc, int buf){
        const uint32_t sb = sbase + buf * STG_B;
        #pragma unroll
        for (int i = 0; i < 9; i++) {
            int o = tid + i * 256;
            if (o < 1536) {
                int s   = o >> 9;
                int rem = o & 511;
                int r   = rem >> 2, seg = rem & 3;
                const void* g = Ap[s] + ((size_t)(m0 + r) * HD + kc*KB + seg*8);
                cp16(sb + s*A_SPL_B + r*80 + seg*16, g);
            } else {
                int o2  = o - 1536;
                int s   = o2 >> 8;
                int rem = o2 & 255;
                int r   = rem >> 2, seg = rem & 3;
                const void* g = Bp[s] + ((size_t)(n0 + r) * HD + kc*KB + seg*8);
                cp16(sb + A_STG_B + s*B_SPL_B + r*80 + seg*16, g);
            }
        }
        CP_COMMIT();
    };

    float acc[2][4][4];
    #pragma unroll
    for (int mt = 0; mt < 2; mt++)
        #pragma unroll
        for (int nt = 0; nt < 4; nt++)
            #pragma unroll
            for (int c = 0; c < 4; c++) acc[mt][nt][c] = 0.0f;

    issue_stage(0, 0);
    issue_stage(1, 1);

    const int SI[6] = {0,0,1,0,1,2};
    const int SJ[6] = {0,1,0,2,1,0};

    const int a_row = wm*32 + (lane & 15);
    const int a_cb  = (lane >> 4) * 16;
    const int b_row = wn*32 + ((lane >> 4) & 1)*8 + (lane & 7);
    const int b_cb  = ((lane >> 3) & 1) * 16;

    for (int kc = 0; kc < NKCH; kc++) {
        CP_WAIT1();
        __syncthreads();
        const uint32_t sb = sbase + (kc & 1) * STG_B;

        #pragma unroll
        for (int ks = 0; ks < 2; ks++) {
            const uint32_t kbyte = ks*32;
            uint32_t afr[3][2][4];
            uint32_t bfr[3][4][2];
            #pragma unroll
            for (int s = 0; s < 3; s++) {
                #pragma unroll
                for (int mt = 0; mt < 2; mt++) {
                    uint32_t ad = sb + s*A_SPL_B + (a_row + mt*16)*80 + kbyte + a_cb;
                    ldsm4(afr[s][mt][0], afr[s][mt][1], afr[s][mt][2], afr[s][mt][3], ad);
                }
                #pragma unroll
                for (int pr = 0; pr < 2; pr++) {
                    uint32_t bd = sb + A_STG_B + s*B_SPL_B + (b_row + pr*16)*80 + kbyte + b_cb;
                    ldsm4(bfr[s][pr*2][0], bfr[s][pr*2][1],
                          bfr[s][pr*2+1][0], bfr[s][pr*2+1][1], bd);
                }
            }
            #pragma unroll
            for (int p = 0; p < 6; p++) {
                const int si = SI[p], sj = SJ[p];
                #pragma unroll
                for (int mt = 0; mt < 2; mt++)
                    #pragma unroll
                    for (int nt = 0; nt < 4; nt++)
                        mma16816(acc[mt][nt], afr[si][mt], bfr[sj][nt]);
            }
        }

        __syncthreads();
        if (kc + 2 < NKCH) issue_stage(kc + 2, kc & 1);
    }

    const int group = blockIdx.x / 12;
    const int ng0   = (blockIdx.x % 12) * 64;

    float* dst; const float* bias; int do_tanh;
    if      (group == 0){ dst = g_Ti; bias = Wab; do_tanh = 1; }
    else if (group == 1){ dst = g_Tj; bias = Uab; do_tanh = 1; }
    else if (group == 2){ dst = g_P;  bias = Db;  do_tanh = 0; }
    else                { dst = g_Q;  bias = 0;   do_tanh = 0; }

    const int er = lane >> 2;
    const int ec = (lane & 3) * 2;

    #pragma unroll
    for (int mt = 0; mt < 2; mt++) {
        #pragma unroll
        for (int nt = 0; nt < 4; nt++) {
            const int c = ng0 + wn*32 + nt*8 + ec;
            float b0 = bias ? bias[c]     : 0.0f;
            float b1 = bias ? bias[c + 1] : 0.0f;
            #pragma unroll
            for (int half = 0; half < 2; half++) {
                const int m = m0 + wm*32 + mt*16 + er + half*8;
                float v0 = acc[mt][nt][half*2 + 0] + b0;
                float v1 = acc[mt][nt][half*2 + 1] + b1;
                if (do_tanh) { v0 = tanh_acc(v0); v1 = tanh_acc(v1); }
                float2 w = make_float2(v0, v1);
                *(float2*)&dst[(size_t)m * HD + c] = w;
            }
        }
    }
}

// ---------------------------------------------------------------------------
// Biaffine v2: partial logits over one h-chunk of 256, h-paired combined
// fraction:  v1*t/(d1) + v2*t/(d2) = (n1*d2 + n2*d1) / (d1*d2),
// n_k = v_k*ti_k + v_k*tj_k,  d_k = 1 + ti_k*tj_k.
// Smem layout [hp][row] float2 (stride 34 -> 16B aligned) for vector LDS.
// Grid (8, 8, NB*NHCH) = 768 CTAs, 128 threads, microtile 2a x 4c.
// ---------------------------------------------------------------------------
__global__ __launch_bounds__(128) void biaffine2_kernel(const float* __restrict__ va)
{
    __shared__ float2 sTj[16][34], sVj[16][34], sTi[16][34], sVi[16][34];

    const int tid = threadIdx.x;
    const int bz  = blockIdx.z;        // b*NHCH + hc
    const int b   = bz / NHCH;
    const int hc  = bz - b * NHCH;
    const int a0  = blockIdx.y * 32;
    const int c0  = blockIdx.x * 32;
    const int la  = tid >> 3;          // 0..15 -> a pair
    const int lc  = tid & 7;           // 0..7  -> c quad

    const float* TjB = g_Tj + (size_t)(b*SEQ + a0) * HD;
    const float* TiB = g_Ti + (size_t)(b*SEQ + c0) * HD;

    float acc[2][4] = {{0.f,0.f,0.f,0.f},{0.f,0.f,0.f,0.f}};

    for (int kb = 0; kb < HCHUNK/32; kb++) {
        const int k0 = hc*HCHUNK + kb*32;

        #pragma unroll
        for (int it = 0; it < 2; it++) {
            const int id  = tid + it*128;     // 0..255
            const int rr  = id >> 3;          // 0..31
            const int seg = id & 7;           // 0..7 (4 h's each)
            const float4 vv = *(const float4*)&va[k0 + seg*4];
            const float4 t  = *(const float4*)&TjB[(size_t)rr*HD + k0 + seg*4];
            sTj[seg*2  ][rr] = make_float2(t.x, t.y);
            sTj[seg*2+1][rr] = make_float2(t.z, t.w);
            sVj[seg*2  ][rr] = make_float2(t.x*vv.x, t.y*vv.y);
            sVj[seg*2+1][rr] = make_float2(t.z*vv.z, t.w*vv.w);
            const float4 u  = *(const float4*)&TiB[(size_t)rr*HD + k0 + seg*4];
            sTi[seg*2  ][rr] = make_float2(u.x, u.y);
            sTi[seg*2+1][rr] = make_float2(u.z, u.w);
            sVi[seg*2  ][rr] = make_float2(u.x*vv.x, u.y*vv.y);
            sVi[seg*2+1][rr] = make_float2(u.z*vv.z, u.w*vv.w);
        }
        __syncthreads();

        #pragma unroll
        for (int hp = 0; hp < 16; hp++) {
            const float4 tj  = *(const float4*)&sTj[hp][la*2];   // {a0h0,a0h1,a1h0,a1h1}
            const float4 vj  = *(const float4*)&sVj[hp][la*2];
            const float4 tiA = *(const float4*)&sTi[hp][lc*4];   // {c0h0,c0h1,c1h0,c1h1}
            const float4 tiB = *(const float4*)&sTi[hp][lc*4+2]; // {c2h0,c2h1,c3h0,c3h1}
            const float4 viA = *(const float4*)&sVi[hp][lc*4];
            const float4 viB = *(const float4*)&sVi[hp][lc*4+2];

            const float ti0[4] = { tiA.x, tiA.z, tiB.x, tiB.z };
            const float ti1[4] = { tiA.y, tiA.w, tiB.y, tiB.w };
            const float vi0[4] = { viA.x, viA.z, viB.x, viB.z };
            const float vi1[4] = { viA.y, viA.w, viB.y, viB.w };

            #pragma unroll
            for (int i = 0; i < 2; i++) {
                const float tj0 = i ? tj.z : tj.x;
                const float tj1 = i ? tj.w : tj.y;
                const float vj0 = i ? vj.z : vj.x;
                const float vj1 = i ? vj.w : vj.y;
                #pragma unroll
                for (int j = 0; j < 4; j++) {
                    const float d1 = fmaf(ti0[j], tj0, 1.0f);
                    const float d2 = fmaf(ti1[j], tj1, 1.0f);
                    const float n1 = vi0[j] + vj0;
                    const float n2 = vi1[j] + vj1;
                    const float num = fmaf(n2, d1, n1*d2);
                    acc[i][j] = fmaf(num, frcp_(d1*d2), acc[i][j]);
                }
            }
        }
        __syncthreads();
    }

    float* pdst = g_part + (size_t)hc * LOGITS_SZ;
    #pragma unroll
    for (int i = 0; i < 2; i++) {
        float4 w = make_float4(acc[i][0], acc[i][1], acc[i][2], acc[i][3]);
        *(float4*)&pdst[((size_t)(b*SEQ + a0 + la*2 + i)) * SEQ + c0 + lc*4] = w;
    }
}

// ---------------------------------------------------------------------------
// Top-4 per row; also sums the 3 h-chunk partials and writes final logits.
// ---------------------------------------------------------------------------
__global__ __launch_bounds__(256) void topk_kernel(float* __restrict__ out)
{
    const int row  = blockIdx.x * 8 + (threadIdx.x >> 5);
    const int lane = threadIdx.x & 31;
    const size_t base = (size_t)row * SEQ;

    float v[8];
    #pragma unroll
    for (int j = 0; j < 8; j++) {
        const size_t o = base + j*32 + lane;
        float s = g_part[o] + g_part[LOGITS_SZ + o] + g_part[2*LOGITS_SZ + o];
        out[o] = s;
        v[j] = s;
    }

    #pragma unroll
    for (int k = 0; k < TOPK; k++) {
        float bv = NEG_INF; int bi = 1 << 30;
        #pragma unroll
        for (int j = 0; j < 8; j++) {
            const int idx = j*32 + lane;
            if (v[j] > bv || (v[j] == bv && idx < bi)) { bv = v[j]; bi = idx; }
        }
        #pragma unroll
        for (int off = 16; off > 0; off >>= 1) {
            float ov = __shfl_down_sync(0xffffffffu, bv, off);
            int   oi = __shfl_down_sync(0xffffffffu, bi, off);
            if (ov > bv || (ov == bv && oi < bi)) { bv = ov; bi = oi; }
        }
        bi = __shfl_sync(0xffffffffu, bi, 0);
        if (lane == 0) g_idx[row*TOPK + k] = bi;
        if ((bi & 31) == lane) {
            const int slot = bi >> 5;
            #pragma unroll
            for (int j = 0; j < 8; j++) if (j == slot) v[j] = NEG_INF;
        }
    }
}

// ---------------------------------------------------------------------------
// Type logits: hidden = tanh(P[row] + Q[head]);  out = hidden @ fc_w^T + fc_b
// ---------------------------------------------------------------------------
__global__ __launch_bounds__(128) void typelogits_kernel(
    const float* __restrict__ fw, const float* __restrict__ fb,
    float* __restrict__ out)
{
    const int row  = blockIdx.x;
    const int m    = threadIdx.x >> 5;
    const int lane = threadIdx.x & 31;
    const int b    = row >> 8;

    const int hidx = g_idx[row*TOPK + m];
    const float* Prow = g_P + (size_t)row * HD;
    const float* Qrow = g_Q + (size_t)(b*SEQ + hidx) * HD;

    float a0=0.f, a1=0.f, a2=0.f, a3=0.f;
    for (int h = lane; h < HD; h += 32) {
        const float t = tanh_acc(Prow[h] + Qrow[h]);
        a0 = fmaf(t, fw[h       ], a0);
        a1 = fmaf(t, fw[h +   HD], a1);
        a2 = fmaf(t, fw[h + 2*HD], a2);
        a3 = fmaf(t, fw[h + 3*HD], a3);
    }
    #pragma unroll
    for (int off = 16; off > 0; off >>= 1) {
        a0 += __shfl_down_sync(0xffffffffu, a0, off);
        a1 += __shfl_down_sync(0xffffffffu, a1, off);
        a2 += __shfl_down_sync(0xffffffffu, a2, off);
        a3 += __shfl_down_sync(0xffffffffu, a3, off);
    }
    if (lane == 0) {
        float* o = out + LOGITS_SZ + (size_t)(row*TOPK + m) * NL;
        o[0] = a0 + fb[0];
        o[1] = a1 + fb[1];
        o[2] = a2 + fb[2];
        o[3] = a3 + fb[3];
    }
}

// ---------------------------------------------------------------------------
extern "C" void kernel_launch(void* const* d_in, const int* in_sizes, int n_in,
                              void* d_out, int out_size)
{
    const float* X   = (const float*)d_in[0];
    const float* Wa  = (const float*)d_in[1];
    const float* Wab = (const float*)d_in[2];
    const float* Ua  = (const float*)d_in[3];
    const float* Uab = (const float*)d_in[4];
    const float* va  = (const float*)d_in[5];
    const float* Dw  = (const float*)d_in[6];
    const float* Db  = (const float*)d_in[7];
    const float* fw  = (const float*)d_in[8];
    const float* fb  = (const float*)d_in[9];
    float* out = (float*)d_out;

    cudaFuncSetAttribute(gemm_mma_kernel,
                         cudaFuncAttributeMaxDynamicSharedMemorySize, GEMM_SMEM);

    splitA_kernel<<<(MROWS*HD + 255)/256, 256>>>(X);
    splitB_kernel<<<(NCOLS*HD + 255)/256, 256>>>(Wa, Ua, Dw);

    dim3 gg(NCOLS/64, MROWS/128);            // 48 x 8 = 384 CTAs
    gemm_mma_kernel<<<gg, 256, GEMM_SMEM>>>(Wab, Uab, Db);

    dim3 g2(SEQ/32, SEQ/32, NB*NHCH);        // 8 x 8 x 12 = 768 CTAs
    biaffine2_kernel<<<g2, 128>>>(va);

    topk_kernel<<<MROWS/8, 256>>>(out);

    typelogits_kernel<<<MROWS, 128>>>(fw, fb, out);
}